// round 11
// baseline (speedup 1.0000x reference)
#include <cuda_runtime.h>

// Problem shape (fixed by the dataset)
#define BB 4
#define CC 32
#define HH 64
#define WW 64
#define HWW (HH * WW)      // 4096
#define NW 64

#define THREADS 128
#define PIXPT 4            // pixels per thread (2 f32x2 pairs)
#define PIX_PER_BLOCK (THREADS * PIXPT)              // 512
#define BLOCKS_PER_SLICE (HWW / PIX_PER_BLOCK)       // 8
#define GRID (BB * CC * BLOCKS_PER_SLICE)            // 1024

typedef unsigned long long u64;

__device__ __forceinline__ float ex2f(float x) {
    float y;
    asm("ex2.approx.ftz.f32 %0, %1;" : "=f"(y) : "f"(x));
    return y;
}
__device__ __forceinline__ u64 pack2(float lo, float hi) {
    u64 r; asm("mov.b64 %0, {%1, %2};" : "=l"(r) : "f"(lo), "f"(hi)); return r;
}
__device__ __forceinline__ void unpack2(u64 v, float& lo, float& hi) {
    asm("mov.b64 {%0, %1}, %2;" : "=f"(lo), "=f"(hi) : "l"(v));
}
__device__ __forceinline__ u64 fma2(u64 a, u64 b, u64 c) {
    u64 r; asm("fma.rn.f32x2 %0, %1, %2, %3;" : "=l"(r) : "l"(a), "l"(b), "l"(c)); return r;
}
__device__ __forceinline__ u64 mul2(u64 a, u64 b) {
    u64 r; asm("mul.rn.f32x2 %0, %1, %2;" : "=l"(r) : "l"(a), "l"(b)); return r;
}

// exponent(base2) = ka*q + kb*x + kc*y   (kd folded into weights)
//   ka = -log2e/(2*sd), kb = -2*ka*mr, kc = -2*ka*mi
//   wr' = wr * 2^(ka*(mr^2+mi^2)),  wi' likewise

__global__ __launch_bounds__(THREADS, 7)
void cplx_rbf_kernel(const float* __restrict__ xr,
                     const float* __restrict__ xi,
                     const float* __restrict__ wr,
                     const float* __restrict__ wi,
                     const float* __restrict__ br,
                     const float* __restrict__ bi,
                     const float* __restrict__ mur,
                     const float* __restrict__ mui,
                     const float* __restrict__ stddev,
                     float* __restrict__ out)
{
    // pre-duplicated (v,v) f32x2 constants, packed for wide LDS broadcasts
    __shared__ __align__(16) u64 s_kab[NW * 2];  // [2k]=ka  [2k+1]=kb   -> LDS.128
    __shared__ __align__(16) u64 s_kcw[NW * 2];  // [2k]=kc  [2k+1]=wr'  -> LDS.128
    __shared__ u64 s_wi[NW];                     // wi'                  -> LDS.64

    const int slice  = blockIdx.x / BLOCKS_PER_SLICE;   // b*C + c
    const int blk_in = blockIdx.x % BLOCKS_PER_SLICE;
    const int c      = slice % CC;
    const int tid    = threadIdx.x;

    if (tid < NW) {
        const float mr = mur[tid];
        const float mi = mui[tid];
        const float ka = -1.4426950408889634f / (2.0f * stddev[tid]);
        const float kb = -2.0f * ka * mr;
        const float kc = -2.0f * ka * mi;
        const float ew = ex2f(ka * (mr * mr + mi * mi));   // 2^kd
        const float wkr = wr[c * NW + tid] * ew;
        const float wki = wi[c * NW + tid] * ew;
        s_kab[2 * tid]     = pack2(ka, ka);
        s_kab[2 * tid + 1] = pack2(kb, kb);
        s_kcw[2 * tid]     = pack2(kc, kc);
        s_kcw[2 * tid + 1] = pack2(wkr, wkr);
        s_wi[tid]          = pack2(wki, wki);
    }
    __syncthreads();

    const int base = slice * HWW + blk_in * PIX_PER_BLOCK + tid * PIXPT;

    const float4 xr4 = *reinterpret_cast<const float4*>(xr + base);
    const float4 xi4 = *reinterpret_cast<const float4*>(xi + base);

    // pixel pairs packed as f32x2
    const u64 xrd0 = pack2(xr4.x, xr4.y);
    const u64 xrd1 = pack2(xr4.z, xr4.w);
    const u64 xid0 = pack2(xi4.x, xi4.y);
    const u64 xid1 = pack2(xi4.z, xi4.w);
    // q = x^2 + y^2 per pixel
    const u64 qd0 = fma2(xrd0, xrd0, mul2(xid0, xid0));
    const u64 qd1 = fma2(xrd1, xrd1, mul2(xid1, xid1));

    u64 srd0 = 0ull, srd1 = 0ull, sid0 = 0ull, sid1 = 0ull;

    const ulonglong2* kab = reinterpret_cast<const ulonglong2*>(s_kab);
    const ulonglong2* kcw = reinterpret_cast<const ulonglong2*>(s_kcw);

    // software pipeline: prefetch k+1's constants while computing k
    ulonglong2 ab = kab[0];
    ulonglong2 cw = kcw[0];
    u64 wki = s_wi[0];

    #pragma unroll 8
    for (int k = 0; k < NW; ++k) {
        // branch-free prefetch (clamped index — harmless re-load on last iter)
        const int kn = (k + 1 < NW) ? (k + 1) : (NW - 1);
        const ulonglong2 ab_n = kab[kn];
        const ulonglong2 cw_n = kcw[kn];
        const u64 wi_n = s_wi[kn];

        const u64 ka = ab.x, kb = ab.y, kc = cw.x, wkr = cw.y;

        u64 t0 = fma2(kb, xrd0, mul2(ka, qd0));
        t0 = fma2(kc, xid0, t0);
        u64 t1 = fma2(kb, xrd1, mul2(ka, qd1));
        t1 = fma2(kc, xid1, t1);

        float a0, a1, b0, b1;
        unpack2(t0, a0, a1);
        unpack2(t1, b0, b1);
        const u64 e0 = pack2(ex2f(a0), ex2f(a1));
        const u64 e1 = pack2(ex2f(b0), ex2f(b1));

        srd0 = fma2(e0, wkr, srd0);
        sid0 = fma2(e0, wki, sid0);
        srd1 = fma2(e1, wkr, srd1);
        sid1 = fma2(e1, wki, sid1);

        ab = ab_n; cw = cw_n; wki = wi_n;
    }

    const float brc = br[c];
    const float bic = bi[c];

    float sr0, sr1, sr2, sr3, si0, si1, si2, si3;
    unpack2(srd0, sr0, sr1);
    unpack2(srd1, sr2, sr3);
    unpack2(sid0, si0, si1);
    unpack2(sid1, si2, si3);

    // Output layout (B,C,H,W,2): interleaved real/imag
    float4 o0, o1;
    o0.x = sr0 + brc; o0.y = si0 + bic;
    o0.z = sr1 + brc; o0.w = si1 + bic;
    o1.x = sr2 + brc; o1.y = si2 + bic;
    o1.z = sr3 + brc; o1.w = si3 + bic;

    float* op = out + (size_t)base * 2;
    *reinterpret_cast<float4*>(op)     = o0;
    *reinterpret_cast<float4*>(op + 4) = o1;
}

extern "C" void kernel_launch(void* const* d_in, const int* in_sizes, int n_in,
                              void* d_out, int out_size)
{
    const float* xr  = (const float*)d_in[0];
    const float* xi  = (const float*)d_in[1];
    const float* wr  = (const float*)d_in[2];
    const float* wi  = (const float*)d_in[3];
    const float* br  = (const float*)d_in[4];
    const float* bi  = (const float*)d_in[5];
    const float* mur = (const float*)d_in[6];
    const float* mui = (const float*)d_in[7];
    const float* sd  = (const float*)d_in[8];
    float* out       = (float*)d_out;

    cplx_rbf_kernel<<<GRID, THREADS>>>(xr, xi, wr, wi, br, bi, mur, mui, sd, out);
}

// round 13
// speedup vs baseline: 1.5050x; 1.5050x over previous
#include <cuda_runtime.h>

// Problem shape (fixed by the dataset)
#define BB 4
#define CC 32
#define HH 64
#define WW 64
#define HWW (HH * WW)      // 4096
#define NW 64

#define THREADS 128
#define PIXPT 4            // pixels per thread (2 f32x2 pairs)
#define PIX_PER_BLOCK (THREADS * PIXPT)              // 512
#define BLOCKS_PER_SLICE (HWW / PIX_PER_BLOCK)       // 8
#define GRID (BB * CC * BLOCKS_PER_SLICE)            // 1024

typedef unsigned long long u64;

__device__ __forceinline__ float ex2f(float x) {
    float y;
    asm("ex2.approx.ftz.f32 %0, %1;" : "=f"(y) : "f"(x));
    return y;
}
__device__ __forceinline__ u64 pack2(float lo, float hi) {
    u64 r; asm("mov.b64 %0, {%1, %2};" : "=l"(r) : "f"(lo), "f"(hi)); return r;
}
__device__ __forceinline__ void unpack2(u64 v, float& lo, float& hi) {
    asm("mov.b64 {%0, %1}, %2;" : "=f"(lo), "=f"(hi) : "l"(v));
}
__device__ __forceinline__ u64 fma2(u64 a, u64 b, u64 c) {
    u64 r; asm("fma.rn.f32x2 %0, %1, %2, %3;" : "=l"(r) : "l"(a), "l"(b), "l"(c)); return r;
}
__device__ __forceinline__ u64 mul2(u64 a, u64 b) {
    u64 r; asm("mul.rn.f32x2 %0, %1, %2;" : "=l"(r) : "l"(a), "l"(b)); return r;
}

// exponent(base2) = ka*q + kb*x + kc*y   (kd folded into weights)
//   ka = -log2e/(2*sd), kb = -2*ka*mr, kc = -2*ka*mi
//   wr' = wr * 2^(ka*(mr^2+mi^2)),  wi' likewise

__global__ __launch_bounds__(THREADS, 7)
void cplx_rbf_kernel(const float* __restrict__ xr,
                     const float* __restrict__ xi,
                     const float* __restrict__ wr,
                     const float* __restrict__ wi,
                     const float* __restrict__ br,
                     const float* __restrict__ bi,
                     const float* __restrict__ mur,
                     const float* __restrict__ mui,
                     const float* __restrict__ stddev,
                     float* __restrict__ out)
{
    // pre-duplicated (v,v) f32x2 constants, packed for wide LDS broadcasts
    __shared__ __align__(16) u64 s_kab[NW * 2];  // [2k]=ka  [2k+1]=kb   -> LDS.128
    __shared__ __align__(16) u64 s_kcw[NW * 2];  // [2k]=kc  [2k+1]=wr'  -> LDS.128
    __shared__ u64 s_wi[NW];                     // wi'                  -> LDS.64

    const int slice  = blockIdx.x / BLOCKS_PER_SLICE;   // b*C + c
    const int blk_in = blockIdx.x % BLOCKS_PER_SLICE;
    const int c      = slice % CC;
    const int tid    = threadIdx.x;

    if (tid < NW) {
        const float mr = mur[tid];
        const float mi = mui[tid];
        const float ka = -1.4426950408889634f / (2.0f * stddev[tid]);
        const float kb = -2.0f * ka * mr;
        const float kc = -2.0f * ka * mi;
        const float ew = ex2f(ka * (mr * mr + mi * mi));   // 2^kd
        const float wkr = wr[c * NW + tid] * ew;
        const float wki = wi[c * NW + tid] * ew;
        s_kab[2 * tid]     = pack2(ka, ka);
        s_kab[2 * tid + 1] = pack2(kb, kb);
        s_kcw[2 * tid]     = pack2(kc, kc);
        s_kcw[2 * tid + 1] = pack2(wkr, wkr);
        s_wi[tid]          = pack2(wki, wki);
    }
    __syncthreads();

    const int base = slice * HWW + blk_in * PIX_PER_BLOCK + tid * PIXPT;

    const float4 xr4 = *reinterpret_cast<const float4*>(xr + base);
    const float4 xi4 = *reinterpret_cast<const float4*>(xi + base);

    // pixel pairs packed as f32x2
    const u64 xrd0 = pack2(xr4.x, xr4.y);
    const u64 xrd1 = pack2(xr4.z, xr4.w);
    const u64 xid0 = pack2(xi4.x, xi4.y);
    const u64 xid1 = pack2(xi4.z, xi4.w);
    // q = x^2 + y^2 per pixel
    const u64 qd0 = fma2(xrd0, xrd0, mul2(xid0, xid0));
    const u64 qd1 = fma2(xrd1, xrd1, mul2(xid1, xid1));

    u64 srd0 = 0ull, srd1 = 0ull, sid0 = 0ull, sid1 = 0ull;

    const ulonglong2* kab = reinterpret_cast<const ulonglong2*>(s_kab);
    const ulonglong2* kcw = reinterpret_cast<const ulonglong2*>(s_kcw);

    // Full unroll: straight-line code lets ptxas hoist LDS loads across
    // iterations with free register renaming (no loop-carried MOV copies).
    #pragma unroll
    for (int k = 0; k < NW; ++k) {
        const ulonglong2 ab = kab[k];     // LDS.128 broadcast
        const ulonglong2 cw = kcw[k];     // LDS.128 broadcast
        const u64 wki = s_wi[k];          // LDS.64  broadcast
        const u64 ka = ab.x, kb = ab.y, kc = cw.x, wkr = cw.y;

        u64 t0 = fma2(kb, xrd0, mul2(ka, qd0));
        t0 = fma2(kc, xid0, t0);
        u64 t1 = fma2(kb, xrd1, mul2(ka, qd1));
        t1 = fma2(kc, xid1, t1);

        float a0, a1, b0, b1;
        unpack2(t0, a0, a1);
        unpack2(t1, b0, b1);
        const u64 e0 = pack2(ex2f(a0), ex2f(a1));
        const u64 e1 = pack2(ex2f(b0), ex2f(b1));

        srd0 = fma2(e0, wkr, srd0);
        sid0 = fma2(e0, wki, sid0);
        srd1 = fma2(e1, wkr, srd1);
        sid1 = fma2(e1, wki, sid1);
    }

    const float brc = br[c];
    const float bic = bi[c];

    float sr0, sr1, sr2, sr3, si0, si1, si2, si3;
    unpack2(srd0, sr0, sr1);
    unpack2(srd1, sr2, sr3);
    unpack2(sid0, si0, si1);
    unpack2(sid1, si2, si3);

    // Output layout (B,C,H,W,2): interleaved real/imag
    float4 o0, o1;
    o0.x = sr0 + brc; o0.y = si0 + bic;
    o0.z = sr1 + brc; o0.w = si1 + bic;
    o1.x = sr2 + brc; o1.y = si2 + bic;
    o1.z = sr3 + brc; o1.w = si3 + bic;

    float* op = out + (size_t)base * 2;
    *reinterpret_cast<float4*>(op)     = o0;
    *reinterpret_cast<float4*>(op + 4) = o1;
}

extern "C" void kernel_launch(void* const* d_in, const int* in_sizes, int n_in,
                              void* d_out, int out_size)
{
    const float* xr  = (const float*)d_in[0];
    const float* xi  = (const float*)d_in[1];
    const float* wr  = (const float*)d_in[2];
    const float* wi  = (const float*)d_in[3];
    const float* br  = (const float*)d_in[4];
    const float* bi  = (const float*)d_in[5];
    const float* mur = (const float*)d_in[6];
    const float* mui = (const float*)d_in[7];
    const float* sd  = (const float*)d_in[8];
    float* out       = (float*)d_out;

    cplx_rbf_kernel<<<GRID, THREADS>>>(xr, xi, wr, wi, br, bi, mur, mui, sd, out);
}